// round 10
// baseline (speedup 1.0000x reference)
#include <cuda_runtime.h>

#define NB 512
#define NG 100
#define NP 100
#define NE 128
#define NH 8
#define NKD 16
#define LDW 132
#define LDS2 132

typedef unsigned long long u64;

// -------- global scratch (static device arrays; no runtime allocation) --------
__device__ float g_q [NB * NG * NE];
__device__ float g_k [NB * NG * NE];
__device__ float g_v [NB * NG * NE];
__device__ float g_oc[NB * NG * NE];
__device__ float g_mh[NB * NG * NE];
__device__ float g_q0[NB * NE];

// -------- f32x2 helpers --------
__device__ __forceinline__ void fma2(u64& d, u64 a, u64 b) {
    asm("fma.rn.f32x2 %0, %1, %2, %0;" : "+l"(d) : "l"(a), "l"(b));
}
__device__ __forceinline__ u64 add2(u64 a, u64 b) {
    u64 d; asm("add.rn.f32x2 %0, %1, %2;" : "=l"(d) : "l"(a), "l"(b)); return d;
}
__device__ __forceinline__ u64 pk(float lo, float hi) {
    u64 d; asm("mov.b64 %0, {%1, %2};" : "=l"(d) : "f"(lo), "f"(hi)); return d;
}
__device__ __forceinline__ float f2sum(u64 a) {
    float lo, hi; asm("mov.b64 {%0, %1}, %2;" : "=f"(lo), "=f"(hi) : "l"(a));
    return lo + hi;
}

// ==================== K0: q0 = in1 @ Wq[0:128] ====================
__global__ void q0_kernel(const float* __restrict__ in1, const float* __restrict__ Wq) {
    int b = blockIdx.x, n = threadIdx.x;
    const float* i1 = in1 + (size_t)b * NE;
    float s = 0.f;
    #pragma unroll 8
    for (int e = 0; e < NE; ++e) s += i1[e] * __ldg(Wq + e * NE + n);
    g_q0[b * NE + n] = s;
}

// ==================== proj: C[b] = A[b](100x128) @ W(128x128) + epilogue ====
// mode 0: none (k, v) ; mode 1: + q0[b] + rem*extra (q) ; mode 2: + extra (mh bias)
__global__ __launch_bounds__(256, 3)
void proj_kernel(const float* __restrict__ A, const float* __restrict__ W,
                 float* __restrict__ C, int mode,
                 const float* __restrict__ rem, const float* __restrict__ extra)
{
    extern __shared__ float swt[];   // WT[n][e], 128 x 132
    const int b = blockIdx.x, t = threadIdx.x, lane = t & 31, ty = t >> 5;

    for (int idx = t; idx < 4096; idx += 256) {
        int n = idx & 127, e = (idx >> 7) << 2;
        float4 v;
        v.x = __ldg(W + (e + 0) * NE + n);
        v.y = __ldg(W + (e + 1) * NE + n);
        v.z = __ldg(W + (e + 2) * NE + n);
        v.w = __ldg(W + (e + 3) * NE + n);
        *(float4*)(swt + n * LDW + e) = v;
    }
    __syncthreads();

    int rbase = ty * 13; if (rbase > 87) rbase = 87;   // rows rbase..rbase+12 <= 99
    const float* Ab = A + (size_t)b * NG * NE + rbase * NE;
    float* Cb = C + (size_t)b * NG * NE;

    #pragma unroll 1
    for (int half = 0; half < 2; ++half) {
        int n0 = half * 64 + lane;
        u64 acc[13][2];
        #pragma unroll
        for (int i = 0; i < 13; ++i) { acc[i][0] = 0ull; acc[i][1] = 0ull; }
        const ulonglong2* w0p = (const ulonglong2*)(swt + n0 * LDW);
        const ulonglong2* w1p = (const ulonglong2*)(swt + (n0 + 32) * LDW);
        #pragma unroll 2
        for (int e4 = 0; e4 < 32; ++e4) {
            ulonglong2 w0 = w0p[e4], w1 = w1p[e4];
            const ulonglong2* ar = (const ulonglong2*)Ab + e4;
            #pragma unroll
            for (int i = 0; i < 13; ++i) {
                ulonglong2 a = ar[i * 32];        // row stride 128 floats = 32 u2
                fma2(acc[i][0], a.x, w0.x); fma2(acc[i][0], a.y, w0.y);
                fma2(acc[i][1], a.x, w1.x); fma2(acc[i][1], a.y, w1.y);
            }
        }
        float ex0 = 0.f, ex1 = 0.f, wl0 = 0.f, wl1 = 0.f;
        if (mode == 1) {
            ex0 = g_q0[b * NE + n0]; ex1 = g_q0[b * NE + n0 + 32];
            wl0 = __ldg(extra + n0); wl1 = __ldg(extra + n0 + 32);
        } else if (mode == 2) {
            ex0 = __ldg(extra + n0); ex1 = __ldg(extra + n0 + 32);
        }
        #pragma unroll
        for (int i = 0; i < 13; ++i) {
            int m = rbase + i;
            float r0 = f2sum(acc[i][0]) + ex0;
            float r1 = f2sum(acc[i][1]) + ex1;
            if (mode == 1) {
                float rv = __ldg(rem + (size_t)b * NG + m);
                r0 += rv * wl0; r1 += rv * wl1;
            }
            Cb[m * NE + n0]      = r0;   // overlap rows (87..90) rewritten with identical values
            Cb[m * NE + n0 + 32] = r1;
        }
    }
}

// ==================== attention: oc = softmax(qk^T/4 + mask) v ====================
__global__ __launch_bounds__(384, 2)
void attn_kernel(const float* __restrict__ mask)
{
    extern __shared__ float sm[];
    float* s_k  = sm;           // 100 x 132
    float* s_v  = sm + 13200;   // 100 x 132
    float* s_ws = sm + 26400;   // 12 x 104
    const int b = blockIdx.x, t = threadIdx.x, lane = t & 31, warp = t >> 5;

    const float* kb = g_k + (size_t)b * NG * NE;
    const float* vb = g_v + (size_t)b * NG * NE;
    for (int idx = t; idx < NG * NE; idx += 384) {
        int r = idx >> 7, c = idx & 127;
        s_k[r * LDS2 + c] = kb[idx];
        s_v[r * LDS2 + c] = vb[idx];
    }
    __syncthreads();

    const float* qb    = g_q + (size_t)b * NG * NE;
    const float* maskb = mask + (size_t)b * NG * NP;
    float* ocb = g_oc + (size_t)b * NG * NE;

    for (int task = warp; task < (NG / 2) * NH; task += 12) {
        int h  = task & 7;
        int gp = task >> 3;
        int g0 = 2 * gp, g1 = g0 + 1;
        const ulonglong2* qp0 = (const ulonglong2*)(qb + g0 * NE + h * NKD);
        const ulonglong2* qp1 = (const ulonglong2*)(qb + g1 * NE + h * NKD);

        u64 x0[4] = {0,0,0,0}, x1[4] = {0,0,0,0};
        #pragma unroll
        for (int half = 0; half < 2; ++half) {
            ulonglong2 qa0 = qp0[2 * half], qa1 = qp0[2 * half + 1];
            ulonglong2 qb0 = qp1[2 * half], qb1 = qp1[2 * half + 1];
            #pragma unroll
            for (int r = 0; r < 4; ++r) {
                int p = lane + 32 * r;
                int pc = p < NP ? p : NP - 1;     // clamp (only r=3 can exceed)
                const ulonglong2* kp = (const ulonglong2*)(s_k + pc * LDS2 + h * NKD);
                ulonglong2 k0 = kp[2 * half], k1 = kp[2 * half + 1];
                fma2(x0[r], qa0.x, k0.x); fma2(x0[r], qa0.y, k0.y);
                fma2(x0[r], qa1.x, k1.x); fma2(x0[r], qa1.y, k1.y);
                fma2(x1[r], qb0.x, k0.x); fma2(x1[r], qb0.y, k0.y);
                fma2(x1[r], qb1.x, k1.x); fma2(x1[r], qb1.y, k1.y);
            }
        }

        float s0[4], s1[4];
        float mx0 = -3e38f, mx1 = -3e38f;
        #pragma unroll
        for (int r = 0; r < 4; ++r) {
            int p = lane + 32 * r;
            float a0 = -3e38f, a1 = -3e38f;
            if (p < NP) {
                a0 = f2sum(x0[r]) * 0.25f + __ldg(maskb + g0 * NP + p);
                a1 = f2sum(x1[r]) * 0.25f + __ldg(maskb + g1 * NP + p);
            }
            s0[r] = a0; s1[r] = a1;
            mx0 = fmaxf(mx0, a0); mx1 = fmaxf(mx1, a1);
        }
        #pragma unroll
        for (int o = 16; o; o >>= 1) {
            mx0 = fmaxf(mx0, __shfl_xor_sync(0xffffffffu, mx0, o));
            mx1 = fmaxf(mx1, __shfl_xor_sync(0xffffffffu, mx1, o));
        }
        float sum0 = 0.f, sum1 = 0.f;
        #pragma unroll
        for (int r = 0; r < 4; ++r) {
            float e0 = (s0[r] > -1e37f) ? __expf(s0[r] - mx0) : 0.f;
            float e1 = (s1[r] > -1e37f) ? __expf(s1[r] - mx1) : 0.f;
            s0[r] = e0; s1[r] = e1; sum0 += e0; sum1 += e1;
        }
        #pragma unroll
        for (int o = 16; o; o >>= 1) {
            sum0 += __shfl_xor_sync(0xffffffffu, sum0, o);
            sum1 += __shfl_xor_sync(0xffffffffu, sum1, o);
        }
        float inv0 = 1.f / sum0, inv1 = 1.f / sum1;

        float* w0 = s_ws + warp * 104;
        int c4 = lane >> 3, pgl = lane & 7;
        #pragma unroll
        for (int gsel = 0; gsel < 2; ++gsel) {
            #pragma unroll
            for (int r = 0; r < 4; ++r) {
                int p = lane + 32 * r;
                if (p < NP) w0[p] = gsel ? s1[r] * inv1 : s0[r] * inv0;
            }
            __syncwarp();
            u64 o0 = 0, o1 = 0;
            #pragma unroll
            for (int pp = 0; pp < 13; ++pp) {
                int p = pgl + 8 * pp;
                if (p < NP) {
                    ulonglong2 vv = *((const ulonglong2*)(s_v + p * LDS2 + h * NKD) + c4);
                    u64 aa = pk(w0[p], w0[p]);
                    fma2(o0, aa, vv.x);
                    fma2(o1, aa, vv.y);
                }
            }
            #pragma unroll
            for (int o = 4; o; o >>= 1) {
                o0 = add2(o0, __shfl_xor_sync(0xffffffffu, o0, o));
                o1 = add2(o1, __shfl_xor_sync(0xffffffffu, o1, o));
            }
            if (pgl == 0) {
                ulonglong2 r0; r0.x = o0; r0.y = o1;
                *(ulonglong2*)(ocb + (gsel ? g1 : g0) * NE + h * NKD + 4 * c4) = r0;
            }
            __syncwarp();
        }
    }
}

// ==================== pointer: probs = softmax(10*tanh(mh @ enc^T / sqrt(128)) + mask)
__global__ __launch_bounds__(384, 2)
void pointer_kernel(const float* __restrict__ mask, const float* __restrict__ enc,
                    float* __restrict__ out)
{
    extern __shared__ float sm[];
    float* s_enc = sm;           // 100 x 132
    float* s_mh  = sm + 13200;   // 100 x 132
    const int b = blockIdx.x, t = threadIdx.x, lane = t & 31, warp = t >> 5;

    const float* encb = enc + (size_t)b * NP * NE;
    const float* mhb  = g_mh + (size_t)b * NG * NE;
    for (int idx = t; idx < NG * NE; idx += 384) {
        int r = idx >> 7, c = idx & 127;
        s_enc[r * LDS2 + c] = encb[idx];
        s_mh[r * LDS2 + c]  = mhb[idx];
    }
    __syncthreads();

    const float* maskb = mask + (size_t)b * NG * NP;
    const float invsq = 0.08838834764831845f;   // 1/sqrt(128)
    float* outb = out + (size_t)b * NG * NP;

    for (int t6 = warp; t6 < NG / 2; t6 += 12) {
        int g0 = 2 * t6, g1 = g0 + 1;
        u64 pacc[2][4];
        #pragma unroll
        for (int g = 0; g < 2; ++g)
            #pragma unroll
            for (int r = 0; r < 4; ++r) pacc[g][r] = 0ull;
        const ulonglong2* ep[4];
        #pragma unroll
        for (int r = 0; r < 4; ++r) {
            int p = lane + 32 * r;
            int pc = p < NP ? p : NP - 1;
            ep[r] = (const ulonglong2*)(s_enc + pc * LDS2);
        }
        const ulonglong2* mp0 = (const ulonglong2*)(s_mh + g0 * LDS2);
        const ulonglong2* mp1 = (const ulonglong2*)(s_mh + g1 * LDS2);
        #pragma unroll 2
        for (int e4 = 0; e4 < 32; ++e4) {
            ulonglong2 m0 = mp0[e4], m1 = mp1[e4];
            #pragma unroll
            for (int r = 0; r < 4; ++r) {
                ulonglong2 ea = ep[r][e4];
                fma2(pacc[0][r], m0.x, ea.x); fma2(pacc[0][r], m0.y, ea.y);
                fma2(pacc[1][r], m1.x, ea.x); fma2(pacc[1][r], m1.y, ea.y);
            }
        }
        #pragma unroll
        for (int g = 0; g < 2; ++g) {
            int gi = g0 + g;
            float sc[4]; float mx = -3e38f;
            #pragma unroll
            for (int r = 0; r < 4; ++r) {
                int p = lane + 32 * r;
                float s = -3e38f;
                if (p < NP)
                    s = 10.f * tanhf(f2sum(pacc[g][r]) * invsq) + __ldg(maskb + gi * NP + p);
                sc[r] = s; mx = fmaxf(mx, s);
            }
            #pragma unroll
            for (int o = 16; o; o >>= 1)
                mx = fmaxf(mx, __shfl_xor_sync(0xffffffffu, mx, o));
            float sum = 0.f;
            #pragma unroll
            for (int r = 0; r < 4; ++r) {
                float e_ = (sc[r] > -1e37f) ? __expf(sc[r] - mx) : 0.f;
                sc[r] = e_; sum += e_;
            }
            #pragma unroll
            for (int o = 16; o; o >>= 1)
                sum += __shfl_xor_sync(0xffffffffu, sum, o);
            float inv = 1.f / sum;
            #pragma unroll
            for (int r = 0; r < 4; ++r) {
                int p = lane + 32 * r;
                if (p < NP) outb[gi * NP + p] = sc[r] * inv;
            }
        }
    }
}

// ==================== launcher ====================
extern "C" void kernel_launch(void* const* d_in, const int* in_sizes, int n_in,
                              void* d_out, int out_size)
{
    const float* in1  = (const float*)d_in[0];
    const float* in2  = (const float*)d_in[1];
    const float* rem  = (const float*)d_in[2];
    const float* mask = (const float*)d_in[3];
    const float* enc  = (const float*)d_in[4];
    const float* Wq   = (const float*)d_in[5];
    const float* Wk   = (const float*)d_in[6];
    const float* Wv   = (const float*)d_in[7];
    const float* Wc   = (const float*)d_in[8];
    const float* bc   = (const float*)d_in[9];
    float* out = (float*)d_out;

    const int smProj = 128 * LDW * 4;                    // 67584
    const int smAttn = (26400 + 12 * 104) * 4;           // 110592
    const int smPtr  = 26400 * 4;                        // 105600
    cudaFuncSetAttribute(proj_kernel,
                         cudaFuncAttributeMaxDynamicSharedMemorySize, smProj);
    cudaFuncSetAttribute(attn_kernel,
                         cudaFuncAttributeMaxDynamicSharedMemorySize, smAttn);
    cudaFuncSetAttribute(pointer_kernel,
                         cudaFuncAttributeMaxDynamicSharedMemorySize, smPtr);

    float *pq, *pk, *pv, *poc, *pmh;
    cudaGetSymbolAddress((void**)&pq,  g_q);
    cudaGetSymbolAddress((void**)&pk,  g_k);
    cudaGetSymbolAddress((void**)&pv,  g_v);
    cudaGetSymbolAddress((void**)&poc, g_oc);
    cudaGetSymbolAddress((void**)&pmh, g_mh);

    q0_kernel<<<NB, 128>>>(in1, Wq);
    proj_kernel<<<NB, 256, smProj>>>(in2, Wq + NE * NE, pq, 1, rem, Wq + 2 * NE * NE);
    proj_kernel<<<NB, 256, smProj>>>(enc, Wk, pk, 0, nullptr, nullptr);
    proj_kernel<<<NB, 256, smProj>>>(enc, Wv, pv, 0, nullptr, nullptr);
    attn_kernel<<<NB, 384, smAttn>>>(mask);
    proj_kernel<<<NB, 256, smProj>>>(poc, Wc, pmh, 2, nullptr, bc);
    pointer_kernel<<<NB, 384, smPtr>>>(mask, enc, out);
}

// round 12
// speedup vs baseline: 2.3945x; 2.3945x over previous
#include <cuda_runtime.h>

#define NB 512
#define NG 100
#define NP 100
#define NE 128
#define NH 8
#define NKD 16
#define LDW 132
#define LDS2 132

typedef unsigned long long u64;

// -------- global scratch (static device arrays) --------
__device__ float g_q [NB * NG * NE];
__device__ float g_k [NB * NG * NE];
__device__ float g_v [NB * NG * NE];
__device__ float g_oc[NB * NG * NE];
__device__ float g_mh[NB * NG * NE];
__device__ float g_q0[NB * NE];

// -------- f32x2 helpers --------
__device__ __forceinline__ void fma2(u64& d, u64 a, u64 b) {
    asm("fma.rn.f32x2 %0, %1, %2, %0;" : "+l"(d) : "l"(a), "l"(b));
}
__device__ __forceinline__ u64 add2(u64 a, u64 b) {
    u64 d; asm("add.rn.f32x2 %0, %1, %2;" : "=l"(d) : "l"(a), "l"(b)); return d;
}
__device__ __forceinline__ u64 pk(float lo, float hi) {
    u64 d; asm("mov.b64 %0, {%1, %2};" : "=l"(d) : "f"(lo), "f"(hi)); return d;
}
__device__ __forceinline__ float f2sum(u64 a) {
    float lo, hi; asm("mov.b64 {%0, %1}, %2;" : "=f"(lo), "=f"(hi) : "l"(a));
    return lo + hi;
}

// ==================== K0: q0 = in1 @ Wq[0:128] ====================
__global__ void q0_kernel(const float* __restrict__ in1, const float* __restrict__ Wq) {
    int b = blockIdx.x, n = threadIdx.x;
    const float* i1 = in1 + (size_t)b * NE;
    float s = 0.f;
    #pragma unroll 8
    for (int e = 0; e < NE; ++e) s += i1[e] * __ldg(Wq + e * NE + n);
    g_q0[b * NE + n] = s;
}

// -------- shared GEMM core: C_rows = sA(100x128) @ WT-half(64x128^T) --------
// 12 warps: warp owns rows rbase..rbase+8 (clamped overlap), cols lane & lane+32 of the half.
__device__ __forceinline__ void gemm_half(const float* __restrict__ sA,
                                          const float* __restrict__ swt,
                                          u64 (&acc)[9][2], int lane, int rbase) {
    const ulonglong2* w0p = (const ulonglong2*)(swt + lane * LDW);
    const ulonglong2* w1p = (const ulonglong2*)(swt + (lane + 32) * LDW);
    const float* a0 = sA + rbase * NE;
    #pragma unroll 2
    for (int e4 = 0; e4 < 32; ++e4) {
        ulonglong2 w0 = w0p[e4], w1 = w1p[e4];
        const float* ar = a0 + 4 * e4;
        #pragma unroll
        for (int i = 0; i < 9; ++i) {
            ulonglong2 a = *(const ulonglong2*)(ar + i * NE);
            fma2(acc[i][0], a.x, w0.x); fma2(acc[i][0], a.y, w0.y);
            fma2(acc[i][1], a.x, w1.x); fma2(acc[i][1], a.y, w1.y);
        }
    }
}

__device__ __forceinline__ void stage_wt_half(const float* __restrict__ W,
                                              float* __restrict__ swt,
                                              int half, int t) {
    for (int idx = t; idx < 2048; idx += 384) {
        int n = idx & 63, e = (idx >> 6) << 2;
        int ng = half * 64 + n;
        float4 v;
        v.x = __ldg(W + (e + 0) * NE + ng);
        v.y = __ldg(W + (e + 1) * NE + ng);
        v.z = __ldg(W + (e + 2) * NE + ng);
        v.w = __ldg(W + (e + 3) * NE + ng);
        *(float4*)(swt + n * LDW + e) = v;
    }
}

// ==================== proj: C[b] = A[b](100x128) @ W(128x128) + epilogue ====
// mode 0: none ; mode 1: + q0[b] + rem*extra (q) ; mode 2: + extra (bias)
__global__ __launch_bounds__(384, 2)
void proj_kernel(const float* __restrict__ A, const float* __restrict__ W,
                 float* __restrict__ C, int mode,
                 const float* __restrict__ rem, const float* __restrict__ extra)
{
    extern __shared__ float sm[];
    float* sA  = sm;             // 100 x 128
    float* swt = sm + 12800;     // 64 x 132
    const int b = blockIdx.x, t = threadIdx.x, lane = t & 31, warp = t >> 5;
    int rbase = warp * 9; if (rbase > 91) rbase = 91;

    const float4* Ab4 = (const float4*)(A + (size_t)b * NG * NE);
    for (int idx = t; idx < 3200; idx += 384)
        ((float4*)sA)[idx] = Ab4[idx];

    float* Cb = C + (size_t)b * NG * NE;

    #pragma unroll 1
    for (int half = 0; half < 2; ++half) {
        __syncthreads();                       // prev-half WT reads / A staging ordered
        stage_wt_half(W, swt, half, t);
        __syncthreads();
        u64 acc[9][2];
        #pragma unroll
        for (int i = 0; i < 9; ++i) { acc[i][0] = 0ull; acc[i][1] = 0ull; }
        gemm_half(sA, swt, acc, lane, rbase);

        int n0 = half * 64 + lane;
        float ex0 = 0.f, ex1 = 0.f, wl0 = 0.f, wl1 = 0.f;
        if (mode == 1) {
            ex0 = g_q0[b * NE + n0]; ex1 = g_q0[b * NE + n0 + 32];
            wl0 = __ldg(extra + n0); wl1 = __ldg(extra + n0 + 32);
        } else if (mode == 2) {
            ex0 = __ldg(extra + n0); ex1 = __ldg(extra + n0 + 32);
        }
        #pragma unroll
        for (int i = 0; i < 9; ++i) {
            int m = rbase + i;
            float r0 = f2sum(acc[i][0]) + ex0;
            float r1 = f2sum(acc[i][1]) + ex1;
            if (mode == 1) {
                float rv = __ldg(rem + (size_t)b * NG + m);
                r0 += rv * wl0; r1 += rv * wl1;
            }
            Cb[m * NE + n0]      = r0;   // overlapping rows rewritten with identical values
            Cb[m * NE + n0 + 32] = r1;
        }
    }
}

// ==================== kv: k = enc@Wk, v = enc@Wv (enc staged once) ====================
__global__ __launch_bounds__(384, 2)
void kv_kernel(const float* __restrict__ enc, const float* __restrict__ Wk,
               const float* __restrict__ Wv)
{
    extern __shared__ float sm[];
    float* sA  = sm;             // enc 100 x 128
    float* swt = sm + 12800;     // 64 x 132
    const int b = blockIdx.x, t = threadIdx.x, lane = t & 31, warp = t >> 5;
    int rbase = warp * 9; if (rbase > 91) rbase = 91;

    const float4* Ab4 = (const float4*)(enc + (size_t)b * NP * NE);
    for (int idx = t; idx < 3200; idx += 384)
        ((float4*)sA)[idx] = Ab4[idx];

    #pragma unroll 1
    for (int mat = 0; mat < 2; ++mat) {
        const float* W = mat ? Wv : Wk;
        float* Cb = (mat ? g_v : g_k) + (size_t)b * NG * NE;
        #pragma unroll 1
        for (int half = 0; half < 2; ++half) {
            __syncthreads();
            stage_wt_half(W, swt, half, t);
            __syncthreads();
            u64 acc[9][2];
            #pragma unroll
            for (int i = 0; i < 9; ++i) { acc[i][0] = 0ull; acc[i][1] = 0ull; }
            gemm_half(sA, swt, acc, lane, rbase);
            int n0 = half * 64 + lane;
            #pragma unroll
            for (int i = 0; i < 9; ++i) {
                int m = rbase + i;
                Cb[m * NE + n0]      = f2sum(acc[i][0]);
                Cb[m * NE + n0 + 32] = f2sum(acc[i][1]);
            }
        }
    }
}

// ==================== attention: oc = softmax(qk^T/4 + mask) v ====================
__global__ __launch_bounds__(384, 2)
void attn_kernel(const float* __restrict__ mask)
{
    extern __shared__ float sm[];
    float* s_k  = sm;           // 100 x 132
    float* s_v  = sm + 13200;   // 100 x 132
    float* s_ws = sm + 26400;   // 12 x 104
    const int b = blockIdx.x, t = threadIdx.x, lane = t & 31, warp = t >> 5;

    const float* kb = g_k + (size_t)b * NG * NE;
    const float* vb = g_v + (size_t)b * NG * NE;
    for (int idx = t; idx < NG * NE; idx += 384) {
        int r = idx >> 7, c = idx & 127;
        s_k[r * LDS2 + c] = kb[idx];
        s_v[r * LDS2 + c] = vb[idx];
    }
    __syncthreads();

    const float* qb    = g_q + (size_t)b * NG * NE;
    const float* maskb = mask + (size_t)b * NG * NP;
    float* ocb = g_oc + (size_t)b * NG * NE;

    for (int task = warp; task < (NG / 2) * NH; task += 12) {
        int h  = task & 7;
        int gp = task >> 3;
        int g0 = 2 * gp, g1 = g0 + 1;
        const ulonglong2* qp0 = (const ulonglong2*)(qb + g0 * NE + h * NKD);
        const ulonglong2* qp1 = (const ulonglong2*)(qb + g1 * NE + h * NKD);

        u64 x0[4] = {0,0,0,0}, x1[4] = {0,0,0,0};
        #pragma unroll
        for (int half = 0; half < 2; ++half) {
            ulonglong2 qa0 = qp0[2 * half], qa1 = qp0[2 * half + 1];
            ulonglong2 qb0 = qp1[2 * half], qb1 = qp1[2 * half + 1];
            #pragma unroll
            for (int r = 0; r < 4; ++r) {
                int p = lane + 32 * r;
                int pc = p < NP ? p : NP - 1;
                const ulonglong2* kp = (const ulonglong2*)(s_k + pc * LDS2 + h * NKD);
                ulonglong2 k0 = kp[2 * half], k1 = kp[2 * half + 1];
                fma2(x0[r], qa0.x, k0.x); fma2(x0[r], qa0.y, k0.y);
                fma2(x0[r], qa1.x, k1.x); fma2(x0[r], qa1.y, k1.y);
                fma2(x1[r], qb0.x, k0.x); fma2(x1[r], qb0.y, k0.y);
                fma2(x1[r], qb1.x, k1.x); fma2(x1[r], qb1.y, k1.y);
            }
        }

        float s0[4], s1[4];
        float mx0 = -3e38f, mx1 = -3e38f;
        #pragma unroll
        for (int r = 0; r < 4; ++r) {
            int p = lane + 32 * r;
            float a0 = -3e38f, a1 = -3e38f;
            if (p < NP) {
                a0 = f2sum(x0[r]) * 0.25f + __ldg(maskb + g0 * NP + p);
                a1 = f2sum(x1[r]) * 0.25f + __ldg(maskb + g1 * NP + p);
            }
            s0[r] = a0; s1[r] = a1;
            mx0 = fmaxf(mx0, a0); mx1 = fmaxf(mx1, a1);
        }
        #pragma unroll
        for (int o = 16; o; o >>= 1) {
            mx0 = fmaxf(mx0, __shfl_xor_sync(0xffffffffu, mx0, o));
            mx1 = fmaxf(mx1, __shfl_xor_sync(0xffffffffu, mx1, o));
        }
        float sum0 = 0.f, sum1 = 0.f;
        #pragma unroll
        for (int r = 0; r < 4; ++r) {
            float e0 = (s0[r] > -1e37f) ? __expf(s0[r] - mx0) : 0.f;
            float e1 = (s1[r] > -1e37f) ? __expf(s1[r] - mx1) : 0.f;
            s0[r] = e0; s1[r] = e1; sum0 += e0; sum1 += e1;
        }
        #pragma unroll
        for (int o = 16; o; o >>= 1) {
            sum0 += __shfl_xor_sync(0xffffffffu, sum0, o);
            sum1 += __shfl_xor_sync(0xffffffffu, sum1, o);
        }
        float inv0 = 1.f / sum0, inv1 = 1.f / sum1;

        float* w0 = s_ws + warp * 104;
        int c4 = lane >> 3, pgl = lane & 7;
        #pragma unroll
        for (int gsel = 0; gsel < 2; ++gsel) {
            #pragma unroll
            for (int r = 0; r < 4; ++r) {
                int p = lane + 32 * r;
                if (p < NP) w0[p] = gsel ? s1[r] * inv1 : s0[r] * inv0;
            }
            __syncwarp();
            u64 o0 = 0, o1 = 0;
            #pragma unroll
            for (int pp = 0; pp < 13; ++pp) {
                int p = pgl + 8 * pp;
                if (p < NP) {
                    ulonglong2 vv = *((const ulonglong2*)(s_v + p * LDS2 + h * NKD) + c4);
                    u64 aa = pk(w0[p], w0[p]);
                    fma2(o0, aa, vv.x);
                    fma2(o1, aa, vv.y);
                }
            }
            #pragma unroll
            for (int o = 4; o; o >>= 1) {
                o0 = add2(o0, __shfl_xor_sync(0xffffffffu, o0, o));
                o1 = add2(o1, __shfl_xor_sync(0xffffffffu, o1, o));
            }
            if (pgl == 0) {
                ulonglong2 r0; r0.x = o0; r0.y = o1;
                *(ulonglong2*)(ocb + (gsel ? g1 : g0) * NE + h * NKD + 4 * c4) = r0;
            }
            __syncwarp();
        }
    }
}

// ==================== pointer: probs = softmax(10*tanh(mh @ enc^T / sqrt(128)) + mask)
__global__ __launch_bounds__(384, 2)
void pointer_kernel(const float* __restrict__ mask, const float* __restrict__ enc,
                    float* __restrict__ out)
{
    extern __shared__ float sm[];
    float* s_enc = sm;           // 100 x 132
    float* s_mh  = sm + 13200;   // 100 x 132
    const int b = blockIdx.x, t = threadIdx.x, lane = t & 31, warp = t >> 5;

    const float* encb = enc + (size_t)b * NP * NE;
    const float* mhb  = g_mh + (size_t)b * NG * NE;
    for (int idx = t; idx < NG * NE; idx += 384) {
        int r = idx >> 7, c = idx & 127;
        s_enc[r * LDS2 + c] = encb[idx];
        s_mh[r * LDS2 + c]  = mhb[idx];
    }
    __syncthreads();

    const float* maskb = mask + (size_t)b * NG * NP;
    const float invsq = 0.08838834764831845f;   // 1/sqrt(128)
    float* outb = out + (size_t)b * NG * NP;

    for (int t6 = warp; t6 < NG / 2; t6 += 12) {
        int g0 = 2 * t6, g1 = g0 + 1;
        u64 pacc[2][4];
        #pragma unroll
        for (int g = 0; g < 2; ++g)
            #pragma unroll
            for (int r = 0; r < 4; ++r) pacc[g][r] = 0ull;
        const ulonglong2* ep[4];
        #pragma unroll
        for (int r = 0; r < 4; ++r) {
            int p = lane + 32 * r;
            int pc = p < NP ? p : NP - 1;
            ep[r] = (const ulonglong2*)(s_enc + pc * LDS2);
        }
        const ulonglong2* mp0 = (const ulonglong2*)(s_mh + g0 * LDS2);
        const ulonglong2* mp1 = (const ulonglong2*)(s_mh + g1 * LDS2);
        #pragma unroll 2
        for (int e4 = 0; e4 < 32; ++e4) {
            ulonglong2 m0 = mp0[e4], m1 = mp1[e4];
            #pragma unroll
            for (int r = 0; r < 4; ++r) {
                ulonglong2 ea = ep[r][e4];
                fma2(pacc[0][r], m0.x, ea.x); fma2(pacc[0][r], m0.y, ea.y);
                fma2(pacc[1][r], m1.x, ea.x); fma2(pacc[1][r], m1.y, ea.y);
            }
        }
        #pragma unroll
        for (int g = 0; g < 2; ++g) {
            int gi = g0 + g;
            float sc[4]; float mx = -3e38f;
            #pragma unroll
            for (int r = 0; r < 4; ++r) {
                int p = lane + 32 * r;
                float s = -3e38f;
                if (p < NP)
                    s = 10.f * tanhf(f2sum(pacc[g][r]) * invsq) + __ldg(maskb + gi * NP + p);
                sc[r] = s; mx = fmaxf(mx, s);
            }
            #pragma unroll
            for (int o = 16; o; o >>= 1)
                mx = fmaxf(mx, __shfl_xor_sync(0xffffffffu, mx, o));
            float sum = 0.f;
            #pragma unroll
            for (int r = 0; r < 4; ++r) {
                float e_ = (sc[r] > -1e37f) ? __expf(sc[r] - mx) : 0.f;
                sc[r] = e_; sum += e_;
            }
            #pragma unroll
            for (int o = 16; o; o >>= 1)
                sum += __shfl_xor_sync(0xffffffffu, sum, o);
            float inv = 1.f / sum;
            #pragma unroll
            for (int r = 0; r < 4; ++r) {
                int p = lane + 32 * r;
                if (p < NP) outb[gi * NP + p] = sc[r] * inv;
            }
        }
    }
}

// ==================== launcher ====================
extern "C" void kernel_launch(void* const* d_in, const int* in_sizes, int n_in,
                              void* d_out, int out_size)
{
    const float* in1  = (const float*)d_in[0];
    const float* in2  = (const float*)d_in[1];
    const float* rem  = (const float*)d_in[2];
    const float* mask = (const float*)d_in[3];
    const float* enc  = (const float*)d_in[4];
    const float* Wq   = (const float*)d_in[5];
    const float* Wk   = (const float*)d_in[6];
    const float* Wv   = (const float*)d_in[7];
    const float* Wc   = (const float*)d_in[8];
    const float* bc   = (const float*)d_in[9];
    float* out = (float*)d_out;

    const int smProj = (12800 + 64 * LDW) * 4;           // 84992
    const int smAttn = (26400 + 12 * 104) * 4;           // 110592
    const int smPtr  = 26400 * 4;                        // 105600
    cudaFuncSetAttribute(proj_kernel,
                         cudaFuncAttributeMaxDynamicSharedMemorySize, smProj);
    cudaFuncSetAttribute(kv_kernel,
                         cudaFuncAttributeMaxDynamicSharedMemorySize, smProj);
    cudaFuncSetAttribute(attn_kernel,
                         cudaFuncAttributeMaxDynamicSharedMemorySize, smAttn);
    cudaFuncSetAttribute(pointer_kernel,
                         cudaFuncAttributeMaxDynamicSharedMemorySize, smPtr);

    float *pq, *poc, *pmh;
    cudaGetSymbolAddress((void**)&pq,  g_q);
    cudaGetSymbolAddress((void**)&poc, g_oc);
    cudaGetSymbolAddress((void**)&pmh, g_mh);

    q0_kernel<<<NB, 128>>>(in1, Wq);
    proj_kernel<<<NB, 384, smProj>>>(in2, Wq + NE * NE, pq, 1, rem, Wq + 2 * NE * NE);
    kv_kernel<<<NB, 384, smProj>>>(enc, Wk, Wv);
    attn_kernel<<<NB, 384, smAttn>>>(mask);
    proj_kernel<<<NB, 384, smProj>>>(poc, Wc, pmh, 2, nullptr, bc);
    pointer_kernel<<<NB, 384, smPtr>>>(mask, enc, out);
}

// round 14
// speedup vs baseline: 2.6026x; 1.0869x over previous
#include <cuda_runtime.h>

#define NB 512
#define NG 100
#define NP 100
#define NE 128
#define NH 8
#define NKD 16
#define LDW 132
#define LDS2 132
#define LDK 102      // kT row stride (attn)
#define LDV 68       // v local row stride (attn)

typedef unsigned long long u64;

// -------- global scratch (static device arrays) --------
__device__ float g_q [NB * NG * NE];
__device__ float g_k [NB * NG * NE];
__device__ float g_v [NB * NG * NE];
__device__ float g_oc[NB * NG * NE];
__device__ float g_mh[NB * NG * NE];

// -------- f32x2 helpers --------
__device__ __forceinline__ void fma2(u64& d, u64 a, u64 b) {
    asm("fma.rn.f32x2 %0, %1, %2, %0;" : "+l"(d) : "l"(a), "l"(b));
}
__device__ __forceinline__ u64 add2(u64 a, u64 b) {
    u64 d; asm("add.rn.f32x2 %0, %1, %2;" : "=l"(d) : "l"(a), "l"(b)); return d;
}
__device__ __forceinline__ u64 pk(float lo, float hi) {
    u64 d; asm("mov.b64 %0, {%1, %2};" : "=l"(d) : "f"(lo), "f"(hi)); return d;
}
__device__ __forceinline__ void unpk(u64 a, float& lo, float& hi) {
    asm("mov.b64 {%0, %1}, %2;" : "=f"(lo), "=f"(hi) : "l"(a));
}
__device__ __forceinline__ float f2sum(u64 a) {
    float lo, hi; unpk(a, lo, hi); return lo + hi;
}

// -------- shared GEMM core: rows rbase..rbase+8 x 64-col half --------
__device__ __forceinline__ void gemm_half(const float* __restrict__ sA,
                                          const float* __restrict__ swt,
                                          u64 (&acc)[9][2], int lane, int rbase) {
    const ulonglong2* w0p = (const ulonglong2*)(swt + lane * LDW);
    const ulonglong2* w1p = (const ulonglong2*)(swt + (lane + 32) * LDW);
    const float* a0 = sA + rbase * NE;
    #pragma unroll 2
    for (int e4 = 0; e4 < 32; ++e4) {
        ulonglong2 w0 = w0p[e4], w1 = w1p[e4];
        const float* ar = a0 + 4 * e4;
        #pragma unroll
        for (int i = 0; i < 9; ++i) {
            ulonglong2 a = *(const ulonglong2*)(ar + i * NE);
            fma2(acc[i][0], a.x, w0.x); fma2(acc[i][0], a.y, w0.y);
            fma2(acc[i][1], a.x, w1.x); fma2(acc[i][1], a.y, w1.y);
        }
    }
}

__device__ __forceinline__ void stage_wt_half(const float* __restrict__ W,
                                              float* __restrict__ swt,
                                              int half, int t) {
    for (int idx = t; idx < 2048; idx += 384) {
        int n = idx & 63, e = (idx >> 6) << 2;
        int ng = half * 64 + n;
        float4 v;
        v.x = __ldg(W + (e + 0) * NE + ng);
        v.y = __ldg(W + (e + 1) * NE + ng);
        v.z = __ldg(W + (e + 2) * NE + ng);
        v.w = __ldg(W + (e + 3) * NE + ng);
        *(float4*)(swt + n * LDW + e) = v;
    }
}

// ==================== proj: C[b] = A[b](100x128) @ W(128x128) + epilogue ====
// mode 0: none ; mode 1: + in1@Wq0 + rem*extra (q) ; mode 2: + extra (bias)
__global__ __launch_bounds__(384, 2)
void proj_kernel(const float* __restrict__ A, const float* __restrict__ W,
                 float* __restrict__ C, int mode,
                 const float* __restrict__ rem, const float* __restrict__ extra,
                 const float* __restrict__ Wq0, const float* __restrict__ in1)
{
    extern __shared__ float sm[];
    float* sA  = sm;             // 100 x 128
    float* swt = sm + 12800;     // 64 x 132
    float* sq0 = sm + 12800 + 64 * LDW;   // 128 (mode 1)
    const int b = blockIdx.x, t = threadIdx.x, lane = t & 31, warp = t >> 5;
    int rbase = warp * 9; if (rbase > 91) rbase = 91;

    const float4* Ab4 = (const float4*)(A + (size_t)b * NG * NE);
    for (int idx = t; idx < 3200; idx += 384)
        ((float4*)sA)[idx] = Ab4[idx];
    if (mode == 1 && t < NE) {
        const float* i1 = in1 + (size_t)b * NE;
        float s = 0.f;
        #pragma unroll 8
        for (int e = 0; e < NE; ++e) s += i1[e] * __ldg(Wq0 + e * NE + t);
        sq0[t] = s;
    }

    float* Cb = C + (size_t)b * NG * NE;

    #pragma unroll 1
    for (int half = 0; half < 2; ++half) {
        __syncthreads();
        stage_wt_half(W, swt, half, t);
        __syncthreads();
        u64 acc[9][2];
        #pragma unroll
        for (int i = 0; i < 9; ++i) { acc[i][0] = 0ull; acc[i][1] = 0ull; }
        gemm_half(sA, swt, acc, lane, rbase);

        int n0 = half * 64 + lane;
        float ex0 = 0.f, ex1 = 0.f, wl0 = 0.f, wl1 = 0.f;
        if (mode == 1) {
            ex0 = sq0[n0]; ex1 = sq0[n0 + 32];
            wl0 = __ldg(extra + n0); wl1 = __ldg(extra + n0 + 32);
        } else if (mode == 2) {
            ex0 = __ldg(extra + n0); ex1 = __ldg(extra + n0 + 32);
        }
        #pragma unroll
        for (int i = 0; i < 9; ++i) {
            int m = rbase + i;
            float r0 = f2sum(acc[i][0]) + ex0;
            float r1 = f2sum(acc[i][1]) + ex1;
            if (mode == 1) {
                float rv = __ldg(rem + (size_t)b * NG + m);
                r0 += rv * wl0; r1 += rv * wl1;
            }
            Cb[m * NE + n0]      = r0;   // overlapping rows rewritten with identical values
            Cb[m * NE + n0 + 32] = r1;
        }
    }
}

// ==================== kv: k = enc@Wk, v = enc@Wv (enc staged once) ====================
__global__ __launch_bounds__(384, 2)
void kv_kernel(const float* __restrict__ enc, const float* __restrict__ Wk,
               const float* __restrict__ Wv)
{
    extern __shared__ float sm[];
    float* sA  = sm;
    float* swt = sm + 12800;
    const int b = blockIdx.x, t = threadIdx.x, lane = t & 31, warp = t >> 5;
    int rbase = warp * 9; if (rbase > 91) rbase = 91;

    const float4* Ab4 = (const float4*)(enc + (size_t)b * NP * NE);
    for (int idx = t; idx < 3200; idx += 384)
        ((float4*)sA)[idx] = Ab4[idx];

    #pragma unroll 1
    for (int mat = 0; mat < 2; ++mat) {
        const float* W = mat ? Wv : Wk;
        float* Cb = (mat ? g_v : g_k) + (size_t)b * NG * NE;
        #pragma unroll 1
        for (int half = 0; half < 2; ++half) {
            __syncthreads();
            stage_wt_half(W, swt, half, t);
            __syncthreads();
            u64 acc[9][2];
            #pragma unroll
            for (int i = 0; i < 9; ++i) { acc[i][0] = 0ull; acc[i][1] = 0ull; }
            gemm_half(sA, swt, acc, lane, rbase);
            int n0 = half * 64 + lane;
            #pragma unroll
            for (int i = 0; i < 9; ++i) {
                int m = rbase + i;
                Cb[m * NE + n0]      = f2sum(acc[i][0]);
                Cb[m * NE + n0 + 32] = f2sum(acc[i][1]);
            }
        }
    }
}

// ==================== attention (4 heads per CTA, kT staging) ====================
__global__ __launch_bounds__(384, 2)
void attn_kernel(const float* __restrict__ mask)
{
    extern __shared__ float sm[];
    float* s_kT = sm;              // 64 x 102 (local head-block cols transposed)
    float* s_v  = sm + 64 * LDK;   // 100 x 68
    float* s_ws = sm + 64 * LDK + 100 * LDV;   // 12 x 208
    const int b = blockIdx.x, hblk = blockIdx.y;   // hblk: head block (4 heads)
    const int t = threadIdx.x, lane = t & 31, warp = t >> 5;

    const float* kb = g_k + (size_t)b * NG * NE + hblk * 64;
    const float* vb = g_v + (size_t)b * NG * NE + hblk * 64;
    for (int idx = t; idx < NG * 16; idx += 384) {
        int p = idx >> 4, e4 = idx & 15;
        float4 kk = *(const float4*)(kb + p * NE + 4 * e4);
        s_kT[(4 * e4 + 0) * LDK + p] = kk.x;
        s_kT[(4 * e4 + 1) * LDK + p] = kk.y;
        s_kT[(4 * e4 + 2) * LDK + p] = kk.z;
        s_kT[(4 * e4 + 3) * LDK + p] = kk.w;
        *(float4*)(s_v + p * LDV + 4 * e4) = *(const float4*)(vb + p * NE + 4 * e4);
    }
    __syncthreads();

    const float* qb    = g_q + (size_t)b * NG * NE;
    const float* maskb = mask + (size_t)b * NG * NP;
    float* ocb = g_oc + (size_t)b * NG * NE;

    // task = 4-g block x local head; 25*4 = 100 tasks over 12 warps
    for (int task = warp; task < (NG / 4) * 4; task += 12) {
        int hl = task & 3;                   // local head 0..3
        int gb = (task >> 2) * 4;
        const float* kTh = s_kT + (hl * NKD) * LDK;
        int colbase = hblk * 64 + hl * NKD;  // global column of this head

        // QK: p-packed; lane owns p = {2l,2l+1} and {64+2l,65+2l}
        u64 a0[4] = {0,0,0,0}, a1[4] = {0,0,0,0};
        #pragma unroll
        for (int e0 = 0; e0 < NKD; e0 += 4) {
            float4 qf[4];
            #pragma unroll
            for (int g = 0; g < 4; ++g)
                qf[g] = *(const float4*)(qb + (gb + g) * NE + colbase + e0);
            #pragma unroll
            for (int e = 0; e < 4; ++e) {
                const float* kr = kTh + (e0 + e) * LDK;
                u64 k0 = *(const u64*)(kr + 2 * lane);
                u64 k1 = *(const u64*)(kr + 64 + 2 * lane);   // lane>=18: garbage, masked
                #pragma unroll
                for (int g = 0; g < 4; ++g) {
                    float qv = (e == 0) ? qf[g].x : (e == 1) ? qf[g].y
                             : (e == 2) ? qf[g].z : qf[g].w;
                    u64 q2 = pk(qv, qv);
                    fma2(a0[g], q2, k0);
                    fma2(a1[g], q2, k1);
                }
            }
        }

        // softmax per g (4 scores per lane, p-packed)
        float w[4][4];
        #pragma unroll
        for (int g = 0; g < 4; ++g) {
            int gi = gb + g;
            float x0, x1, x2, x3;
            unpk(a0[g], x0, x1);
            unpk(a1[g], x2, x3);
            float2 mA = *(const float2*)(maskb + gi * NP + 2 * lane);
            x0 = x0 * 0.25f + mA.x;
            x1 = x1 * 0.25f + mA.y;
            if (lane < 18) {
                float2 mB = *(const float2*)(maskb + gi * NP + 64 + 2 * lane);
                x2 = x2 * 0.25f + mB.x;
                x3 = x3 * 0.25f + mB.y;
            } else { x2 = -3e38f; x3 = -3e38f; }
            float mx = fmaxf(fmaxf(x0, x1), fmaxf(x2, x3));
            #pragma unroll
            for (int o = 16; o; o >>= 1)
                mx = fmaxf(mx, __shfl_xor_sync(0xffffffffu, mx, o));
            x0 = __expf(x0 - mx);
            x1 = __expf(x1 - mx);
            x2 = (lane < 18) ? __expf(x2 - mx) : 0.f;
            x3 = (lane < 18) ? __expf(x3 - mx) : 0.f;
            float sum = x0 + x1 + x2 + x3;
            #pragma unroll
            for (int o = 16; o; o >>= 1)
                sum += __shfl_xor_sync(0xffffffffu, sum, o);
            float inv = 1.f / sum;
            w[g][0] = x0 * inv; w[g][1] = x1 * inv;
            w[g][2] = x2 * inv; w[g][3] = x3 * inv;
        }

        // AV in 2 sub-batches of 2 g via the per-warp ws slot
        float* wsl = s_ws + warp * 208;
        int c4 = lane >> 3, pgl = lane & 7;
        #pragma unroll
        for (int sb = 0; sb < 2; ++sb) {
            int ga = 2 * sb, gbd = 2 * sb + 1;
            float* w0 = wsl;
            float* w1 = wsl + 104;
            *(float2*)(w0 + 2 * lane) = make_float2(w[ga][0], w[ga][1]);
            *(float2*)(w1 + 2 * lane) = make_float2(w[gbd][0], w[gbd][1]);
            if (lane < 18) {
                *(float2*)(w0 + 64 + 2 * lane) = make_float2(w[ga][2], w[ga][3]);
                *(float2*)(w1 + 64 + 2 * lane) = make_float2(w[gbd][2], w[gbd][3]);
            }
            __syncwarp();
            u64 o00 = 0, o01 = 0, o10 = 0, o11 = 0;
            #pragma unroll
            for (int pp = 0; pp < 13; ++pp) {
                int p = pgl + 8 * pp;
                if (p < NP) {
                    ulonglong2 vv = *((const ulonglong2*)(s_v + p * LDV + hl * NKD) + c4);
                    u64 aa = pk(w0[p], w0[p]);
                    u64 cc = pk(w1[p], w1[p]);
                    fma2(o00, aa, vv.x); fma2(o01, aa, vv.y);
                    fma2(o10, cc, vv.x); fma2(o11, cc, vv.y);
                }
            }
            #pragma unroll
            for (int o = 4; o; o >>= 1) {
                o00 = add2(o00, __shfl_xor_sync(0xffffffffu, o00, o));
                o01 = add2(o01, __shfl_xor_sync(0xffffffffu, o01, o));
                o10 = add2(o10, __shfl_xor_sync(0xffffffffu, o10, o));
                o11 = add2(o11, __shfl_xor_sync(0xffffffffu, o11, o));
            }
            if (pgl == 0) {
                ulonglong2 r0; r0.x = o00; r0.y = o01;
                ulonglong2 r1; r1.x = o10; r1.y = o11;
                *(ulonglong2*)(ocb + (gb + ga)  * NE + colbase + 4 * c4) = r0;
                *(ulonglong2*)(ocb + (gb + gbd) * NE + colbase + 4 * c4) = r1;
            }
            __syncwarp();
        }
    }
}

// ==================== pointer: probs = softmax(10*tanh(mh @ enc^T / sqrt(128)) + mask)
__global__ __launch_bounds__(384, 2)
void pointer_kernel(const float* __restrict__ mask, const float* __restrict__ enc,
                    float* __restrict__ out)
{
    extern __shared__ float sm[];
    float* s_enc = sm;           // 100 x 132
    float* s_mh  = sm + 13200;   // 100 x 132
    const int b = blockIdx.x, t = threadIdx.x, lane = t & 31, warp = t >> 5;

    const float* encb = enc + (size_t)b * NP * NE;
    const float* mhb  = g_mh + (size_t)b * NG * NE;
    for (int idx = t; idx < NG * NE; idx += 384) {
        int r = idx >> 7, c = idx & 127;
        s_enc[r * LDS2 + c] = encb[idx];
        s_mh[r * LDS2 + c]  = mhb[idx];
    }
    __syncthreads();

    const float* maskb = mask + (size_t)b * NG * NP;
    const float invsq = 0.08838834764831845f;   // 1/sqrt(128)
    float* outb = out + (size_t)b * NG * NP;

    for (int t6 = warp; t6 < NG / 2; t6 += 12) {
        int g0 = 2 * t6, g1 = g0 + 1;
        u64 pacc[2][4];
        #pragma unroll
        for (int g = 0; g < 2; ++g)
            #pragma unroll
            for (int r = 0; r < 4; ++r) pacc[g][r] = 0ull;
        const ulonglong2* ep[4];
        #pragma unroll
        for (int r = 0; r < 4; ++r) {
            int p = lane + 32 * r;
            int pc = p < NP ? p : NP - 1;
            ep[r] = (const ulonglong2*)(s_enc + pc * LDS2);
        }
        const ulonglong2* mp0 = (const ulonglong2*)(s_mh + g0 * LDS2);
        const ulonglong2* mp1 = (const ulonglong2*)(s_mh + g1 * LDS2);
        #pragma unroll 2
        for (int e4 = 0; e4 < 32; ++e4) {
            ulonglong2 m0 = mp0[e4], m1 = mp1[e4];
            #pragma unroll
            for (int r = 0; r < 4; ++r) {
                ulonglong2 ea = ep[r][e4];
                fma2(pacc[0][r], m0.x, ea.x); fma2(pacc[0][r], m0.y, ea.y);
                fma2(pacc[1][r], m1.x, ea.x); fma2(pacc[1][r], m1.y, ea.y);
            }
        }
        #pragma unroll
        for (int g = 0; g < 2; ++g) {
            int gi = g0 + g;
            float sc[4]; float mx = -3e38f;
            #pragma unroll
            for (int r = 0; r < 4; ++r) {
                int p = lane + 32 * r;
                float s = -3e38f;
                if (p < NP)
                    s = 10.f * tanhf(f2sum(pacc[g][r]) * invsq) + __ldg(maskb + gi * NP + p);
                sc[r] = s; mx = fmaxf(mx, s);
            }
            #pragma unroll
            for (int o = 16; o; o >>= 1)
                mx = fmaxf(mx, __shfl_xor_sync(0xffffffffu, mx, o));
            float sum = 0.f;
            #pragma unroll
            for (int r = 0; r < 4; ++r) {
                float e_ = (sc[r] > -1e37f) ? __expf(sc[r] - mx) : 0.f;
                sc[r] = e_; sum += e_;
            }
            #pragma unroll
            for (int o = 16; o; o >>= 1)
                sum += __shfl_xor_sync(0xffffffffu, sum, o);
            float inv = 1.f / sum;
            #pragma unroll
            for (int r = 0; r < 4; ++r) {
                int p = lane + 32 * r;
                if (p < NP) outb[gi * NP + p] = sc[r] * inv;
            }
        }
    }
}

// ==================== launcher ====================
extern "C" void kernel_launch(void* const* d_in, const int* in_sizes, int n_in,
                              void* d_out, int out_size)
{
    const float* in1  = (const float*)d_in[0];
    const float* in2  = (const float*)d_in[1];
    const float* rem  = (const float*)d_in[2];
    const float* mask = (const float*)d_in[3];
    const float* enc  = (const float*)d_in[4];
    const float* Wq   = (const float*)d_in[5];
    const float* Wk   = (const float*)d_in[6];
    const float* Wv   = (const float*)d_in[7];
    const float* Wc   = (const float*)d_in[8];
    const float* bc   = (const float*)d_in[9];
    float* out = (float*)d_out;

    const int smProj = (12800 + 64 * LDW + 128) * 4;     // 85504
    const int smAttn = (64 * LDK + 100 * LDV + 12 * 208) * 4;  // 63296
    const int smPtr  = 26400 * 4;                        // 105600
    cudaFuncSetAttribute(proj_kernel,
                         cudaFuncAttributeMaxDynamicSharedMemorySize, smProj);
    cudaFuncSetAttribute(kv_kernel,
                         cudaFuncAttributeMaxDynamicSharedMemorySize, smProj);
    cudaFuncSetAttribute(attn_kernel,
                         cudaFuncAttributeMaxDynamicSharedMemorySize, smAttn);
    cudaFuncSetAttribute(pointer_kernel,
                         cudaFuncAttributeMaxDynamicSharedMemorySize, smPtr);

    float *pq, *poc, *pmh;
    cudaGetSymbolAddress((void**)&pq,  g_q);
    cudaGetSymbolAddress((void**)&poc, g_oc);
    cudaGetSymbolAddress((void**)&pmh, g_mh);

    proj_kernel<<<NB, 384, smProj>>>(in2, Wq + NE * NE, pq, 1, rem,
                                     Wq + 2 * NE * NE, Wq, in1);
    kv_kernel<<<NB, 384, smProj>>>(enc, Wk, Wv);
    attn_kernel<<<dim3(NB, 2), 384, smAttn>>>(mask);
    proj_kernel<<<NB, 384, smProj>>>(poc, Wc, pmh, 2, nullptr, bc, nullptr, nullptr);
    pointer_kernel<<<NB, 384, smPtr>>>(mask, enc, out);
}

// round 16
// speedup vs baseline: 2.7197x; 1.0450x over previous
#include <cuda_runtime.h>

#define NB 512
#define NG 100
#define NP 100
#define NE 128
#define NH 8
#define NKD 16
#define LDW 132
#define LDK 102      // kT row stride (attn)
#define LDV 68       // v local row stride (attn)

typedef unsigned long long u64;

// -------- global scratch --------
__device__ float g_q [NB * NG * NE];
__device__ float g_k [NB * NG * NE];
__device__ float g_v [NB * NG * NE];
__device__ float g_oc[NB * NG * NE];
__device__ float g_mh[NB * NG * NE];

// -------- f32x2 helpers --------
__device__ __forceinline__ void fma2(u64& d, u64 a, u64 b) {
    asm("fma.rn.f32x2 %0, %1, %2, %0;" : "+l"(d) : "l"(a), "l"(b));
}
__device__ __forceinline__ u64 add2(u64 a, u64 b) {
    u64 d; asm("add.rn.f32x2 %0, %1, %2;" : "=l"(d) : "l"(a), "l"(b)); return d;
}
__device__ __forceinline__ u64 pk(float lo, float hi) {
    u64 d; asm("mov.b64 %0, {%1, %2};" : "=l"(d) : "f"(lo), "f"(hi)); return d;
}
__device__ __forceinline__ void unpk(u64 a, float& lo, float& hi) {
    asm("mov.b64 {%0, %1}, %2;" : "=f"(lo), "=f"(hi) : "l"(a));
}
__device__ __forceinline__ float f2sum(u64 a) {
    float lo, hi; unpk(a, lo, hi); return lo + hi;
}

// -------- GEMM core: rows rbase..rbase+8 x 64-col half (conflict-free) --------
__device__ __forceinline__ void gemm_half(const float* __restrict__ sA,
                                          const float* __restrict__ swt,
                                          u64 (&acc)[9][2], int lane, int rbase) {
    const ulonglong2* w0p = (const ulonglong2*)(swt + lane * LDW);
    const ulonglong2* w1p = (const ulonglong2*)(swt + (lane + 32) * LDW);
    const float* a0 = sA + rbase * NE;
    #pragma unroll 2
    for (int e4 = 0; e4 < 32; ++e4) {
        ulonglong2 w0 = w0p[e4], w1 = w1p[e4];
        const float* ar = a0 + 4 * e4;
        #pragma unroll
        for (int i = 0; i < 9; ++i) {
            ulonglong2 a = *(const ulonglong2*)(ar + i * NE);
            fma2(acc[i][0], a.x, w0.x); fma2(acc[i][0], a.y, w0.y);
            fma2(acc[i][1], a.x, w1.x); fma2(acc[i][1], a.y, w1.y);
        }
    }
}

// stage transposed weight half: swt[n][e] = W[e][half*64+n]
__device__ __forceinline__ void stage_wt_half(const float* __restrict__ W,
                                              float* __restrict__ swt,
                                              int half, int t) {
    for (int idx = t; idx < 2048; idx += 384) {
        int n = idx & 63, e = (idx >> 6) << 2;
        int ng = half * 64 + n;
        float4 v;
        v.x = __ldg(W + (e + 0) * NE + ng);
        v.y = __ldg(W + (e + 1) * NE + ng);
        v.z = __ldg(W + (e + 2) * NE + ng);
        v.w = __ldg(W + (e + 3) * NE + ng);
        *(float4*)(swt + n * LDW + e) = v;
    }
}

// stage row-block (already WT-layout source, e.g. enc): swt[n][e] = S[(half*64+n)][e]
__device__ __forceinline__ void stage_rows_half(const float* __restrict__ S,
                                                float* __restrict__ swt,
                                                int half, int t, int nrows) {
    for (int idx = t; idx < 2048; idx += 384) {
        int n = idx >> 5, e4 = idx & 31;
        int r = half * 64 + n;
        int rc = r < nrows ? r : nrows - 1;     // clamp (garbage masked later)
        *(float4*)(swt + n * LDW + 4 * e4) = *(const float4*)(S + rc * NE + 4 * e4);
    }
}

// ==================== fused q/k/v projections: grid (NB, 3) ====================
// y=0: q = [in1|in2|rem] @ Wq  ; y=1: k = enc@Wk ; y=2: v = enc@Wv
__global__ __launch_bounds__(384, 2)
void qkv_kernel(const float* __restrict__ in2, const float* __restrict__ enc,
                const float* __restrict__ Wq, const float* __restrict__ Wk,
                const float* __restrict__ Wv, const float* __restrict__ rem,
                const float* __restrict__ in1)
{
    extern __shared__ float sm[];
    float* sA  = sm;                      // 100 x 128
    float* swt = sm + 12800;              // 64 x 132
    float* sq0 = sm + 12800 + 64 * LDW;   // 128
    const int b = blockIdx.x, by = blockIdx.y;
    const int t = threadIdx.x, lane = t & 31, warp = t >> 5;
    int rbase = warp * 9; if (rbase > 91) rbase = 91;

    const float* A = (by == 0) ? (in2 + (size_t)b * NG * NE)
                               : (enc + (size_t)b * NP * NE);
    const float* W = (by == 0) ? (Wq + NE * NE) : (by == 1) ? Wk : Wv;
    float* Cb = ((by == 0) ? g_q : (by == 1) ? g_k : g_v) + (size_t)b * NG * NE;

    const float4* Ab4 = (const float4*)A;
    for (int idx = t; idx < 3200; idx += 384)
        ((float4*)sA)[idx] = Ab4[idx];
    if (by == 0 && t < NE) {
        const float* i1 = in1 + (size_t)b * NE;
        float s = 0.f;
        #pragma unroll 8
        for (int e = 0; e < NE; ++e) s += i1[e] * __ldg(Wq + e * NE + t);
        sq0[t] = s;
    }

    #pragma unroll 1
    for (int half = 0; half < 2; ++half) {
        __syncthreads();
        stage_wt_half(W, swt, half, t);
        __syncthreads();
        u64 acc[9][2];
        #pragma unroll
        for (int i = 0; i < 9; ++i) { acc[i][0] = 0ull; acc[i][1] = 0ull; }
        gemm_half(sA, swt, acc, lane, rbase);

        int n0 = half * 64 + lane;
        float ex0 = 0.f, ex1 = 0.f, wl0 = 0.f, wl1 = 0.f;
        if (by == 0) {
            ex0 = sq0[n0]; ex1 = sq0[n0 + 32];
            wl0 = __ldg(Wq + 2 * NE * NE + n0);
            wl1 = __ldg(Wq + 2 * NE * NE + n0 + 32);
        }
        #pragma unroll
        for (int i = 0; i < 9; ++i) {
            int m = rbase + i;
            float r0 = f2sum(acc[i][0]) + ex0;
            float r1 = f2sum(acc[i][1]) + ex1;
            if (by == 0) {
                float rv = __ldg(rem + (size_t)b * NG + m);
                r0 += rv * wl0; r1 += rv * wl1;
            }
            Cb[m * NE + n0]      = r0;   // overlap rows rewritten identically
            Cb[m * NE + n0 + 32] = r1;
        }
    }
}

// ==================== mh projection: mh = oc @ Wc + bc ====================
__global__ __launch_bounds__(384, 2)
void proj_mh_kernel(const float* __restrict__ Wc, const float* __restrict__ bc)
{
    extern __shared__ float sm[];
    float* sA  = sm;
    float* swt = sm + 12800;
    const int b = blockIdx.x, t = threadIdx.x, lane = t & 31, warp = t >> 5;
    int rbase = warp * 9; if (rbase > 91) rbase = 91;

    const float4* Ab4 = (const float4*)(g_oc + (size_t)b * NG * NE);
    for (int idx = t; idx < 3200; idx += 384)
        ((float4*)sA)[idx] = Ab4[idx];
    float* Cb = g_mh + (size_t)b * NG * NE;

    #pragma unroll 1
    for (int half = 0; half < 2; ++half) {
        __syncthreads();
        stage_wt_half(Wc, swt, half, t);
        __syncthreads();
        u64 acc[9][2];
        #pragma unroll
        for (int i = 0; i < 9; ++i) { acc[i][0] = 0ull; acc[i][1] = 0ull; }
        gemm_half(sA, swt, acc, lane, rbase);
        int n0 = half * 64 + lane;
        float ex0 = __ldg(bc + n0), ex1 = __ldg(bc + n0 + 32);
        #pragma unroll
        for (int i = 0; i < 9; ++i) {
            int m = rbase + i;
            Cb[m * NE + n0]      = f2sum(acc[i][0]) + ex0;
            Cb[m * NE + n0 + 32] = f2sum(acc[i][1]) + ex1;
        }
    }
}

// ==================== attention (4 heads per CTA, kT staging) ====================
__global__ __launch_bounds__(384, 2)
void attn_kernel(const float* __restrict__ mask)
{
    extern __shared__ float sm[];
    float* s_kT = sm;              // 64 x 102
    float* s_v  = sm + 64 * LDK;   // 100 x 68
    float* s_ws = sm + 64 * LDK + 100 * LDV;   // 12 x 208
    const int b = blockIdx.x, hblk = blockIdx.y;
    const int t = threadIdx.x, lane = t & 31, warp = t >> 5;

    const float* kb = g_k + (size_t)b * NG * NE + hblk * 64;
    const float* vb = g_v + (size_t)b * NG * NE + hblk * 64;
    for (int idx = t; idx < NG * 16; idx += 384) {
        int p = idx >> 4, e4 = idx & 15;
        float4 kk = *(const float4*)(kb + p * NE + 4 * e4);
        s_kT[(4 * e4 + 0) * LDK + p] = kk.x;
        s_kT[(4 * e4 + 1) * LDK + p] = kk.y;
        s_kT[(4 * e4 + 2) * LDK + p] = kk.z;
        s_kT[(4 * e4 + 3) * LDK + p] = kk.w;
        *(float4*)(s_v + p * LDV + 4 * e4) = *(const float4*)(vb + p * NE + 4 * e4);
    }
    __syncthreads();

    const float* qb    = g_q + (size_t)b * NG * NE;
    const float* maskb = mask + (size_t)b * NG * NP;
    float* ocb = g_oc + (size_t)b * NG * NE;

    for (int task = warp; task < (NG / 4) * 4; task += 12) {
        int hl = task & 3;
        int gb = (task >> 2) * 4;
        const float* kTh = s_kT + (hl * NKD) * LDK;
        int colbase = hblk * 64 + hl * NKD;

        u64 a0[4] = {0,0,0,0}, a1[4] = {0,0,0,0};
        #pragma unroll
        for (int e0 = 0; e0 < NKD; e0 += 4) {
            float4 qf[4];
            #pragma unroll
            for (int g = 0; g < 4; ++g)
                qf[g] = *(const float4*)(qb + (gb + g) * NE + colbase + e0);
            #pragma unroll
            for (int e = 0; e < 4; ++e) {
                const float* kr = kTh + (e0 + e) * LDK;
                u64 k0 = *(const u64*)(kr + 2 * lane);
                u64 k1 = *(const u64*)(kr + 64 + 2 * lane);
                #pragma unroll
                for (int g = 0; g < 4; ++g) {
                    float qv = (e == 0) ? qf[g].x : (e == 1) ? qf[g].y
                             : (e == 2) ? qf[g].z : qf[g].w;
                    u64 q2 = pk(qv, qv);
                    fma2(a0[g], q2, k0);
                    fma2(a1[g], q2, k1);
                }
            }
        }

        float w[4][4];
        #pragma unroll
        for (int g = 0; g < 4; ++g) {
            int gi = gb + g;
            float x0, x1, x2, x3;
            unpk(a0[g], x0, x1);
            unpk(a1[g], x2, x3);
            float2 mA = *(const float2*)(maskb + gi * NP + 2 * lane);
            x0 = x0 * 0.25f + mA.x;
            x1 = x1 * 0.25f + mA.y;
            if (lane < 18) {
                float2 mB = *(const float2*)(maskb + gi * NP + 64 + 2 * lane);
                x2 = x2 * 0.25f + mB.x;
                x3 = x3 * 0.25f + mB.y;
            } else { x2 = -3e38f; x3 = -3e38f; }
            float mx = fmaxf(fmaxf(x0, x1), fmaxf(x2, x3));
            #pragma unroll
            for (int o = 16; o; o >>= 1)
                mx = fmaxf(mx, __shfl_xor_sync(0xffffffffu, mx, o));
            x0 = __expf(x0 - mx);
            x1 = __expf(x1 - mx);
            x2 = (lane < 18) ? __expf(x2 - mx) : 0.f;
            x3 = (lane < 18) ? __expf(x3 - mx) : 0.f;
            float sum = x0 + x1 + x2 + x3;
            #pragma unroll
            for (int o = 16; o; o >>= 1)
                sum += __shfl_xor_sync(0xffffffffu, sum, o);
            float inv = 1.f / sum;
            w[g][0] = x0 * inv; w[g][1] = x1 * inv;
            w[g][2] = x2 * inv; w[g][3] = x3 * inv;
        }

        float* wsl = s_ws + warp * 208;
        int c4 = lane >> 3, pgl = lane & 7;
        #pragma unroll
        for (int sb = 0; sb < 2; ++sb) {
            int ga = 2 * sb, gbd = 2 * sb + 1;
            float* w0 = wsl;
            float* w1 = wsl + 104;
            *(float2*)(w0 + 2 * lane) = make_float2(w[ga][0], w[ga][1]);
            *(float2*)(w1 + 2 * lane) = make_float2(w[gbd][0], w[gbd][1]);
            if (lane < 18) {
                *(float2*)(w0 + 64 + 2 * lane) = make_float2(w[ga][2], w[ga][3]);
                *(float2*)(w1 + 64 + 2 * lane) = make_float2(w[gbd][2], w[gbd][3]);
            }
            __syncwarp();
            u64 o00 = 0, o01 = 0, o10 = 0, o11 = 0;
            #pragma unroll
            for (int pp = 0; pp < 13; ++pp) {
                int p = pgl + 8 * pp;
                if (p < NP) {
                    ulonglong2 vv = *((const ulonglong2*)(s_v + p * LDV + hl * NKD) + c4);
                    u64 aa = pk(w0[p], w0[p]);
                    u64 cc = pk(w1[p], w1[p]);
                    fma2(o00, aa, vv.x); fma2(o01, aa, vv.y);
                    fma2(o10, cc, vv.x); fma2(o11, cc, vv.y);
                }
            }
            #pragma unroll
            for (int o = 4; o; o >>= 1) {
                o00 = add2(o00, __shfl_xor_sync(0xffffffffu, o00, o));
                o01 = add2(o01, __shfl_xor_sync(0xffffffffu, o01, o));
                o10 = add2(o10, __shfl_xor_sync(0xffffffffu, o10, o));
                o11 = add2(o11, __shfl_xor_sync(0xffffffffu, o11, o));
            }
            if (pgl == 0) {
                ulonglong2 r0; r0.x = o00; r0.y = o01;
                ulonglong2 r1; r1.x = o10; r1.y = o11;
                *(ulonglong2*)(ocb + (gb + ga)  * NE + colbase + 4 * c4) = r0;
                *(ulonglong2*)(ocb + (gb + gbd) * NE + colbase + 4 * c4) = r1;
            }
            __syncwarp();
        }
    }
}

// ==================== pointer: gemm_half-style score GEMM + softmax ====================
__global__ __launch_bounds__(384, 2)
void pointer_kernel(const float* __restrict__ mask, const float* __restrict__ enc,
                    float* __restrict__ out)
{
    extern __shared__ float sm[];
    float* sA  = sm;            // mh 100 x 128
    float* swt = sm + 12800;    // enc half 64 x 132
    const int b = blockIdx.x, t = threadIdx.x, lane = t & 31, warp = t >> 5;
    int rbase = warp * 9; if (rbase > 91) rbase = 91;

    const float4* Ab4 = (const float4*)(g_mh + (size_t)b * NG * NE);
    for (int idx = t; idx < 3200; idx += 384)
        ((float4*)sA)[idx] = Ab4[idx];

    const float* encb = enc + (size_t)b * NP * NE;
    float sc[9][4];

    #pragma unroll 1
    for (int half = 0; half < 2; ++half) {
        __syncthreads();
        stage_rows_half(encb, swt, half, t, NP);
        __syncthreads();
        u64 acc[9][2];
        #pragma unroll
        for (int i = 0; i < 9; ++i) { acc[i][0] = 0ull; acc[i][1] = 0ull; }
        gemm_half(sA, swt, acc, lane, rbase);
        #pragma unroll
        for (int i = 0; i < 9; ++i) {
            sc[i][2 * half + 0] = f2sum(acc[i][0]);
            sc[i][2 * half + 1] = f2sum(acc[i][1]);
        }
    }
    // lane now holds scores for p = {lane, lane+32, lane+64, lane+96} per row
    // (sc index: [0]=p=lane(half0 col lane), [1]=lane+32, [2]=lane+64, [3]=lane+96)

    const float* maskb = mask + (size_t)b * NG * NP;
    const float invsq = 0.08838834764831845f;   // 1/sqrt(128)
    float* outb = out + (size_t)b * NG * NP;

    #pragma unroll
    for (int i = 0; i < 9; ++i) {
        int g = rbase + i;
        float x[4]; float mx = -3e38f;
        #pragma unroll
        for (int r = 0; r < 4; ++r) {
            int p = lane + 32 * r;
            float s = -3e38f;
            if (p < NP)
                s = 10.f * tanhf(sc[i][r] * invsq) + __ldg(maskb + g * NP + p);
            x[r] = s; mx = fmaxf(mx, s);
        }
        #pragma unroll
        for (int o = 16; o; o >>= 1)
            mx = fmaxf(mx, __shfl_xor_sync(0xffffffffu, mx, o));
        float sum = 0.f;
        #pragma unroll
        for (int r = 0; r < 4; ++r) {
            float e_ = (x[r] > -1e37f) ? __expf(x[r] - mx) : 0.f;
            x[r] = e_; sum += e_;
        }
        #pragma unroll
        for (int o = 16; o; o >>= 1)
            sum += __shfl_xor_sync(0xffffffffu, sum, o);
        float inv = 1.f / sum;
        #pragma unroll
        for (int r = 0; r < 4; ++r) {
            int p = lane + 32 * r;
            if (p < NP) outb[g * NP + p] = x[r] * inv;   // overlap rows rewritten identically
        }
    }
}

// ==================== launcher ====================
extern "C" void kernel_launch(void* const* d_in, const int* in_sizes, int n_in,
                              void* d_out, int out_size)
{
    const float* in1  = (const float*)d_in[0];
    const float* in2  = (const float*)d_in[1];
    const float* rem  = (const float*)d_in[2];
    const float* mask = (const float*)d_in[3];
    const float* enc  = (const float*)d_in[4];
    const float* Wq   = (const float*)d_in[5];
    const float* Wk   = (const float*)d_in[6];
    const float* Wv   = (const float*)d_in[7];
    const float* Wc   = (const float*)d_in[8];
    const float* bc   = (const float*)d_in[9];
    float* out = (float*)d_out;

    const int smProj = (12800 + 64 * LDW + 128) * 4;           // 85504
    const int smAttn = (64 * LDK + 100 * LDV + 12 * 208) * 4;  // 63296
    cudaFuncSetAttribute(qkv_kernel,
                         cudaFuncAttributeMaxDynamicSharedMemorySize, smProj);
    cudaFuncSetAttribute(proj_mh_kernel,
                         cudaFuncAttributeMaxDynamicSharedMemorySize, smProj);
    cudaFuncSetAttribute(attn_kernel,
                         cudaFuncAttributeMaxDynamicSharedMemorySize, smAttn);
    cudaFuncSetAttribute(pointer_kernel,
                         cudaFuncAttributeMaxDynamicSharedMemorySize, smProj);

    qkv_kernel<<<dim3(NB, 3), 384, smProj>>>(in2, enc, Wq, Wk, Wv, rem, in1);
    attn_kernel<<<dim3(NB, 2), 384, smAttn>>>(mask);
    proj_mh_kernel<<<NB, 384, smProj>>>(Wc, bc);
    pointer_kernel<<<NB, 384, smProj>>>(mask, enc, out);
}